// round 4
// baseline (speedup 1.0000x reference)
#include <cuda_runtime.h>
#include <cuda_bf16.h>
#include <math.h>

#define BATCH 2
#define DIM   256
#define NC    19
#define TOPK  256
#define HF    128
#define WF    128
#define HH    512
#define WW    512
#define SPIX  (HF*WF)            // 16384
#define NPIX  (BATCH*HH*WW)      // 524288
#define EPSV  1e-12f
#define GAMMA_MAX 0.999f
#define NB    8192               // histogram bins over w in [0,1)
#define CCAP  2048               // shared candidate capacity (threshold bin)

#define TRANS_BLOCKS 8192        // 512 * 8 * 2
#define WT_BLOCKS    2048        // NPIX / 256

// ---------------- scratch (static device memory; zero-init at load) ----------------
__device__ float g_fT[(size_t)BATCH*SPIX*DIM];   // features transposed [B, HF*WF, DIM]
__device__ float g_cw[(size_t)NC*NPIX];          // per-class weight lists
__device__ int   g_cidx[(size_t)NC*NPIX];        // per-class pixel-index lists
__device__ int   g_hist[NC*NB];                  // per-class weight histograms
__device__ int   g_cnt[NC];                      // per-class list counts
__device__ int   g_tb[NC];                       // threshold bin per class

// ---------------- helpers ----------------
__device__ __forceinline__ void src_coord(int o, int &i0, int &i1, float &f) {
    float s = (o + 0.5f) * 0.25f - 0.5f;
    float fl = floorf(s);
    f = s - fl;
    int i = (int)fl;
    i0 = min(max(i, 0), HF - 1);
    i1 = min(max(i + 1, 0), HF - 1);
}

__device__ __forceinline__ int w_bin(float w) {
    int b = (int)(w * (float)NB);
    return min(NB - 1, max(0, b));
}

// ================= K1: fused transpose + weights/list/histogram =================
__global__ void k_main(const float* __restrict__ f,
                       const float* __restrict__ weight,
                       const int* __restrict__ labels) {
    if (blockIdx.x < TRANS_BLOCKS) {
        // ---- NCHW -> NHWC transpose ----
        __shared__ float tile[32][33];
        int i = blockIdx.x;
        int s0 = (i & 511) * 32;
        int d0 = ((i >> 9) & 7) * 32;
        int b  = i >> 12;
        int tx = threadIdx.x & 31;
        int ty = threadIdx.x >> 5;           // 0..7
        #pragma unroll
        for (int r = ty; r < 32; r += 8)
            tile[r][tx] = f[((size_t)(b * DIM + d0 + r)) * SPIX + s0 + tx];
        __syncthreads();
        #pragma unroll
        for (int r = ty; r < 32; r += 8)
            g_fT[((size_t)(b * SPIX + s0 + r)) * DIM + d0 + tx] = tile[tx][r];
    } else {
        // ---- per-pixel weight + per-class list append + histogram ----
        __shared__ int s_cnt[NC];
        __shared__ int s_base[NC];
        int n = (blockIdx.x - TRANS_BLOCKS) * 256 + threadIdx.x;
        if (threadIdx.x < NC) s_cnt[threadIdx.x] = 0;
        __syncthreads();

        int lab = labels[n];
        bool valid = ((unsigned)lab < NC);
        float w = 0.f;
        int r = 0, key = 0;
        if (valid) {
            int b   = n >> 18;
            int rem = n & (HH * WW - 1);
            int Y = rem >> 9;
            int X = rem & 511;
            int y0, y1, x0, x1; float fy, fx;
            src_coord(Y, y0, y1, fy);
            src_coord(X, x0, x1, fx);
            const float* wp = weight + ((size_t)(b * NC + lab)) * SPIX;
            float v00 = __ldg(wp + y0 * WF + x0);
            float v01 = __ldg(wp + y0 * WF + x1);
            float v10 = __ldg(wp + y1 * WF + x0);
            float v11 = __ldg(wp + y1 * WF + x1);
            w = (1.f - fy) * ((1.f - fx) * v00 + fx * v01)
              +        fy  * ((1.f - fx) * v10 + fx * v11);
            r = atomicAdd(&s_cnt[lab], 1);
            key = lab * NB + w_bin(w);
        }
        // warp-aggregated histogram atomics
        unsigned am = __ballot_sync(0xFFFFFFFFu, valid);
        if (valid) {
            unsigned grp = __match_any_sync(am, key);
            int leader = __ffs(grp) - 1;
            if ((threadIdx.x & 31) == leader)
                atomicAdd(&g_hist[key], __popc(grp));
        }
        __syncthreads();
        if (threadIdx.x < NC && s_cnt[threadIdx.x] > 0)
            s_base[threadIdx.x] = atomicAdd(&g_cnt[threadIdx.x], s_cnt[threadIdx.x]);
        __syncthreads();
        if (valid) {
            size_t o = (size_t)lab * NPIX + (size_t)(s_base[lab] + r);
            g_cw[o]   = w;
            g_cidx[o] = n;
        }
    }
}

// ================= K2: threshold bin from histogram + hist cleanup =================
__global__ void k_thresh() {
    int c = blockIdx.x;
    int t = threadIdx.x;                 // 256 threads, 32 bins each (top-down)
    __shared__ int P[256];
    __shared__ int s_j;
    int* h = g_hist + c * NB;
    int lo = NB - (t + 1) * 32;
    int s = 0;
    #pragma unroll
    for (int b = 0; b < 32; b++) s += h[lo + b];
    P[t] = s;
    __syncthreads();
    // inclusive scan over 256 chunk sums (descending-bin order)
    for (int off = 1; off < 256; off <<= 1) {
        int v = (t >= off) ? P[t - off] : 0;
        __syncthreads();
        P[t] += v;
        __syncthreads();
    }
    int total = g_cnt[c];
    if (total <= TOPK) {
        if (t == 0) g_tb[c] = -1;        // take everything
    } else {
        if (P[t] >= TOPK && (t == 0 || P[t - 1] < TOPK)) s_j = t;
        __syncthreads();
        if (t == 0) {
            int j = s_j;
            int acc = (j == 0) ? 0 : P[j - 1];
            for (int b = NB - 32 * j - 1; b >= NB - 32 * (j + 1); b--) {
                acc += h[b];
                if (acc >= TOPK) { g_tb[c] = b; break; }
            }
        }
    }
    __syncthreads();
    // cleanup for next graph replay
    for (int i = t; i < NB; i += 256) h[i] = 0;
}

// ================= K3: partition + fill + accumulate + finalize =================
__global__ void __launch_bounds__(1024) k_tail(
        const float* __restrict__ prototypes,
        const float* __restrict__ update_count,
        float* __restrict__ out, int out_size) {
    int c = blockIdx.x;
    int t = threadIdx.x;
    __shared__ float s_w[TOPK];
    __shared__ int   s_i[TOPK];
    __shared__ float s_cw[CCAP];
    __shared__ int   s_ci[CCAP];
    __shared__ unsigned hist[2048];
    __shared__ float red[1024];
    __shared__ float red2[256];
    __shared__ int s_nsel, s_ncand;
    __shared__ int s_rem, s_tbin, s_abv, s_done;
    __shared__ unsigned s_pmask, s_pval;

    int L  = g_cnt[c];
    int tb = g_tb[c];
    if (t == 0) { s_nsel = 0; s_ncand = 0; }
    __syncthreads();

    // ---- phase A: scan class list, partition ----
    const float* cw = g_cw  + (size_t)c * NPIX;
    const int*   ci = g_cidx + (size_t)c * NPIX;
    for (int i = t; i < L; i += 1024) {
        float w = cw[i];
        int bin = w_bin(w);
        if (bin > tb) {
            int p = atomicAdd(&s_nsel, 1);
            if (p < TOPK) { s_w[p] = w; s_i[p] = ci[i]; }
        } else if (bin == tb) {
            int q = atomicAdd(&s_ncand, 1);
            if (q < CCAP) { s_cw[q] = w; s_ci[q] = ci[i]; }
        }
    }
    __syncthreads();

    // ---- phase B: fill remaining slots from threshold-bin candidates ----
    int above = min(s_nsel, TOPK);
    int r = TOPK - above;
    int L2 = min(s_ncand, CCAP);
    if (r > 0) {
        if (L2 <= r) {
            for (int i = t; i < L2; i += 1024) {
                s_w[above + i] = s_cw[i];
                s_i[above + i] = s_ci[i];
            }
            if (t == 0) s_nsel = above + L2;
            __syncthreads();
        } else {
            // exact top-r via 3-level radix select on float bits (w >= 0)
            if (t == 0) { s_rem = r; s_pmask = 0u; s_pval = 0u; s_done = 0; }
            __syncthreads();
            const int shifts[3] = {21, 10, 0};
            const int nbins[3]  = {2048, 2048, 1024};
            for (int lev = 0; lev < 3; lev++) {
                int sh = shifts[lev];
                unsigned bm = (unsigned)nbins[lev] - 1u;
                for (int i = t; i < 2048; i += 1024) hist[i] = 0u;
                __syncthreads();
                unsigned pm = s_pmask, pv = s_pval;
                for (int i = t; i < L2; i += 1024) {
                    unsigned key = __float_as_uint(s_cw[i]);
                    if ((key & pm) == pv) atomicAdd(&hist[(key >> sh) & bm], 1u);
                }
                __syncthreads();
                if (t == 0) {
                    int cum = 0;
                    int b = nbins[lev] - 1;
                    for (; b >= 0; b--) { cum += (int)hist[b]; if (cum >= s_rem) break; }
                    s_tbin = b;
                    s_abv  = cum - (int)hist[b];
                }
                __syncthreads();
                int tbin = s_tbin;
                for (int i = t; i < L2; i += 1024) {
                    unsigned key = __float_as_uint(s_cw[i]);
                    if ((key & pm) == pv && (int)((key >> sh) & bm) > tbin) {
                        int p = atomicAdd(&s_nsel, 1);
                        if (p < TOPK) { s_w[p] = s_cw[i]; s_i[p] = s_ci[i]; }
                    }
                }
                __syncthreads();
                if (t == 0) {
                    s_rem -= s_abv;
                    s_pval  = s_pval | ((unsigned)tbin << sh);
                    s_pmask = s_pmask | (bm << sh);
                    if ((int)hist[tbin] == s_rem) s_done = 1;
                }
                __syncthreads();
                if (s_done || lev == 2) {
                    unsigned fpm = s_pmask, fpv = s_pval;
                    for (int i = t; i < L2; i += 1024) {
                        unsigned key = __float_as_uint(s_cw[i]);
                        if ((key & fpm) == fpv) {
                            int p = atomicAdd(&s_nsel, 1);
                            if (p < TOPK) { s_w[p] = s_cw[i]; s_i[p] = s_ci[i]; }
                        }
                    }
                    break;
                }
            }
            __syncthreads();
        }
    }

    // ---- phase C: pad + weight sum ----
    int nsel = min(s_nsel, TOPK);
    for (int i = t; i < TOPK; i += 1024)
        if (i >= nsel) { s_w[i] = 0.f; s_i[i] = 0; }
    __syncthreads();
    red[t] = (t < TOPK) ? s_w[t] : 0.f;
    __syncthreads();
    for (int s = 512; s > 0; s >>= 1) {
        if (t < s) red[t] += red[t + s];
        __syncthreads();
    }
    float wsum = red[0];
    __syncthreads();

    // ---- phase D: weighted feature accumulation ----
    int d    = t & (DIM - 1);
    int part = t >> 8;
    float acc = 0.f;
    int k0 = part * (TOPK / 4);
    #pragma unroll 4
    for (int k = k0; k < k0 + TOPK / 4; k++) {
        float w = s_w[k];
        if (w > 0.f) {
            int n   = s_i[k];
            int b   = n >> 18;
            int rem = n & (HH * WW - 1);
            int Y = rem >> 9;
            int X = rem & 511;
            int y0, y1, x0, x1; float fy, fx;
            src_coord(Y, y0, y1, fy);
            src_coord(X, x0, x1, fx);
            const float* base = g_fT + ((size_t)b * SPIX) * DIM;
            const float* p00 = base + ((size_t)(y0 * WF + x0)) * DIM;
            const float* p01 = base + ((size_t)(y0 * WF + x1)) * DIM;
            const float* p10 = base + ((size_t)(y1 * WF + x0)) * DIM;
            const float* p11 = base + ((size_t)(y1 * WF + x1)) * DIM;
            float w00 = (1.f - fy) * (1.f - fx);
            float w01 = (1.f - fy) * fx;
            float w10 = fy * (1.f - fx);
            float w11 = fy * fx;
            float v = w00 * __ldg(p00 + d) + w01 * __ldg(p01 + d)
                    + w10 * __ldg(p10 + d) + w11 * __ldg(p11 + d);
            acc += w * v;
        }
    }
    red[t] = acc;
    __syncthreads();

    // ---- phase E: normalize, EMA, normalize, write ----
    float proto = 0.f;
    if (t < DIM) {
        float tot = red[d] + red[d + 256] + red[d + 512] + red[d + 768];
        proto = tot / fmaxf(wsum, EPSV);
        red2[d] = proto * proto;
    }
    __syncthreads();
    for (int s = 128; s > 0; s >>= 1) {
        if (t < s) red2[t] += red2[t + s];
        __syncthreads();
    }
    float nrm = sqrtf(red2[0]);
    __syncthreads();

    bool has = (L > 0) && (wsum > 0.f);
    float uc = update_count[c];
    float gamma = (uc == 0.f) ? 0.f : fminf(1.f - 1.f / (uc + 1.f), GAMMA_MAX);
    float nv = 0.f;
    if (t < DIM) {
        proto = proto / fmaxf(nrm, EPSV);
        float oldp = prototypes[c * DIM + d];
        nv = has ? (gamma * oldp + (1.f - gamma) * proto) : oldp;
        red2[d] = nv * nv;
    }
    __syncthreads();
    for (int s = 128; s > 0; s >>= 1) {
        if (t < s) red2[t] += red2[t + s];
        __syncthreads();
    }
    float nrm2 = sqrtf(red2[0]);
    if (t < DIM)
        out[c * DIM + d] = nv / fmaxf(nrm2, EPSV);
    if (t == 0) {
        if (out_size >= NC * DIM + NC)
            out[NC * DIM + c] = uc + (has ? 1.f : 0.f);
        g_cnt[c] = 0;   // cleanup for next graph replay
    }
}

// ---------------- launch ----------------
extern "C" void kernel_launch(void* const* d_in, const int* in_sizes, int n_in,
                              void* d_out, int out_size) {
    const float* features     = (const float*)d_in[0];
    const float* weight       = (const float*)d_in[1];
    const float* prototypes   = (const float*)d_in[2];
    const float* update_count = (const float*)d_in[3];
    const int*   labels       = (const int*)d_in[4];
    float* out = (float*)d_out;

    k_main<<<TRANS_BLOCKS + WT_BLOCKS, 256>>>(features, weight, labels);
    k_thresh<<<NC, 256>>>();
    k_tail<<<NC, 1024>>>(prototypes, update_count, out, out_size);
}

// round 5
// speedup vs baseline: 3.3821x; 3.3821x over previous
#include <cuda_runtime.h>
#include <cuda_bf16.h>
#include <math.h>

#define BATCH 2
#define DIM   256
#define NC    19
#define TOPK  256
#define HF    128
#define WF    128
#define HH    512
#define WW    512
#define SPIX  (HF*WF)            // 16384
#define NPIX  (BATCH*HH*WW)      // 524288
#define EPSV  1e-12f
#define GAMMA_MAX 0.999f
#define NB    8192               // histogram bins over w in [0,1)
#define CCAP  2048               // shared candidate capacity (threshold bin)

#define TRANS_BLOCKS 8192        // 512 * 8 * 2
#define WT_BLOCKS    2048        // NPIX / 256

// ---------------- scratch (static device memory; zero-init at load) ----------------
__device__ float g_fT[(size_t)BATCH*SPIX*DIM];   // features transposed [B, HF*WF, DIM]
__device__ float g_cw[(size_t)NC*NPIX];          // per-class weight lists
__device__ int   g_cidx[(size_t)NC*NPIX];        // per-class pixel-index lists
__device__ int   g_cnt[NC];                      // per-class list counts

// ---------------- helpers ----------------
__device__ __forceinline__ void src_coord(int o, int &i0, int &i1, float &f) {
    float s = (o + 0.5f) * 0.25f - 0.5f;
    float fl = floorf(s);
    f = s - fl;
    int i = (int)fl;
    i0 = min(max(i, 0), HF - 1);
    i1 = min(max(i + 1, 0), HF - 1);
}

__device__ __forceinline__ int w_bin(float w) {
    int b = (int)(w * (float)NB);
    return min(NB - 1, max(0, b));
}

// ================= K1: fused transpose + weights/list append =================
__global__ void k_main(const float* __restrict__ f,
                       const float* __restrict__ weight,
                       const int* __restrict__ labels) {
    if (blockIdx.x < TRANS_BLOCKS) {
        // ---- NCHW -> NHWC transpose ----
        __shared__ float tile[32][33];
        int i = blockIdx.x;
        int s0 = (i & 511) * 32;
        int d0 = ((i >> 9) & 7) * 32;
        int b  = i >> 12;
        int tx = threadIdx.x & 31;
        int ty = threadIdx.x >> 5;           // 0..7
        #pragma unroll
        for (int r = ty; r < 32; r += 8)
            tile[r][tx] = f[((size_t)(b * DIM + d0 + r)) * SPIX + s0 + tx];
        __syncthreads();
        #pragma unroll
        for (int r = ty; r < 32; r += 8)
            g_fT[((size_t)(b * SPIX + s0 + r)) * DIM + d0 + tx] = tile[tx][r];
    } else {
        // ---- per-pixel weight + per-class list append ----
        __shared__ int s_cnt[NC];
        __shared__ int s_base[NC];
        int n = (blockIdx.x - TRANS_BLOCKS) * 256 + threadIdx.x;
        if (threadIdx.x < NC) s_cnt[threadIdx.x] = 0;
        __syncthreads();

        int lab = labels[n];
        bool valid = ((unsigned)lab < NC);
        float w = 0.f;
        int r = 0;
        if (valid) {
            int b   = n >> 18;
            int rem = n & (HH * WW - 1);
            int Y = rem >> 9;
            int X = rem & 511;
            int y0, y1, x0, x1; float fy, fx;
            src_coord(Y, y0, y1, fy);
            src_coord(X, x0, x1, fx);
            const float* wp = weight + ((size_t)(b * NC + lab)) * SPIX;
            float v00 = __ldg(wp + y0 * WF + x0);
            float v01 = __ldg(wp + y0 * WF + x1);
            float v10 = __ldg(wp + y1 * WF + x0);
            float v11 = __ldg(wp + y1 * WF + x1);
            w = (1.f - fy) * ((1.f - fx) * v00 + fx * v01)
              +        fy  * ((1.f - fx) * v10 + fx * v11);
            r = atomicAdd(&s_cnt[lab], 1);
        }
        __syncthreads();
        if (threadIdx.x < NC && s_cnt[threadIdx.x] > 0)
            s_base[threadIdx.x] = atomicAdd(&g_cnt[threadIdx.x], s_cnt[threadIdx.x]);
        __syncthreads();
        if (valid) {
            size_t o = (size_t)lab * NPIX + (size_t)(s_base[lab] + r);
            g_cw[o]   = w;
            g_cidx[o] = n;
        }
    }
}

// ================= K2: hist + threshold + partition + fill + accumulate + finalize =================
__global__ void __launch_bounds__(1024) k_tail(
        const float* __restrict__ prototypes,
        const float* __restrict__ update_count,
        float* __restrict__ out, int out_size) {
    int c = blockIdx.x;
    int t = threadIdx.x;

    __shared__ int   hist[NB];        // 32 KB; reused as candidate store later
    __shared__ float s_w[TOPK];
    __shared__ int   s_i[TOPK];
    __shared__ int   P[1024];         // scan workspace
    __shared__ float red[1024];       // reductions (reused)
    __shared__ int s_nsel, s_ncand, s_tb, s_above;

    int L = g_cnt[c];
    const float* cw = g_cw   + (size_t)c * NPIX;
    const int*   ci = g_cidx + (size_t)c * NPIX;

    #pragma unroll
    for (int i = t; i < NB; i += 1024) hist[i] = 0;
    if (t == 0) { s_nsel = 0; s_ncand = 0; s_tb = -1; s_above = 0; }
    __syncthreads();

    // ---- pass 1: local histogram of this class's weights ----
    for (int i = t; i < L; i += 1024)
        atomicAdd(&hist[w_bin(cw[i])], 1);
    __syncthreads();

    // ---- parallel threshold-bin discovery (only needed if L > TOPK) ----
    if (L > TOPK) {
        int base = NB - (t + 1) * 8;          // 8 bins per thread, top-down chunks
        int s = 0;
        #pragma unroll
        for (int b = 0; b < 8; b++) s += hist[base + b];
        P[t] = s;
        __syncthreads();
        // Hillis-Steele inclusive scan over 1024 chunk sums (descending-bin order)
        #pragma unroll
        for (int off = 1; off < 1024; off <<= 1) {
            int v = (t >= off) ? P[t - off] : 0;
            __syncthreads();
            P[t] += v;
            __syncthreads();
        }
        if (P[t] >= TOPK && (t == 0 || P[t - 1] < TOPK)) {
            int acc = (t == 0) ? 0 : P[t - 1];
            for (int b = NB - t * 8 - 1; b >= base; b--) {
                int h = hist[b];
                if (acc + h >= TOPK) { s_tb = b; s_above = acc; break; }
                acc += h;
            }
        }
        __syncthreads();
    }
    int tb = s_tb;                     // -1 => take everything

    // ---- pass 2: partition (hist storage reused for candidates) ----
    float* s_cw = (float*)hist;        // [0 .. CCAP)
    int*   s_ci = hist + CCAP;         // [CCAP .. 2*CCAP)
    for (int i = t; i < L; i += 1024) {
        float w = cw[i];
        int bin = w_bin(w);
        if (bin > tb) {
            int p = atomicAdd(&s_nsel, 1);     // guaranteed < TOPK
            s_w[p] = w; s_i[p] = ci[i];
        } else if (bin == tb) {
            int q = atomicAdd(&s_ncand, 1);
            if (q < CCAP) { s_cw[q] = w; s_ci[q] = ci[i]; }
        }
    }
    __syncthreads();

    // ---- parallel rank select to fill remaining slots from threshold bin ----
    int above = s_nsel;
    int r = TOPK - above;
    int L2 = min(s_ncand, CCAP);
    int nsel = above + ((r > 0) ? min(r, L2) : 0);
    if (r > 0) {
        for (int i = t; i < L2; i += 1024) {
            float wi = s_cw[i];
            int rank = 0;
            for (int j = 0; j < L2; j++) {
                float wj = s_cw[j];
                rank += (wj > wi) || (wj == wi && j < i);
            }
            if (rank < r) { s_w[above + rank] = wi; s_i[above + rank] = s_ci[i]; }
        }
    }
    __syncthreads();

    // ---- pad unused slots ----
    for (int i = t; i < TOPK; i += 1024)
        if (i >= nsel) { s_w[i] = 0.f; s_i[i] = 0; }
    __syncthreads();

    // ---- weight sum ----
    red[t] = (t < TOPK) ? s_w[t] : 0.f;
    __syncthreads();
    for (int s = 512; s > 0; s >>= 1) {
        if (t < s) red[t] += red[t + s];
        __syncthreads();
    }
    float wsum = red[0];
    __syncthreads();

    // ---- weighted feature accumulation ----
    int d    = t & (DIM - 1);
    int part = t >> 8;
    float acc = 0.f;
    int k0 = part * (TOPK / 4);
    #pragma unroll 4
    for (int k = k0; k < k0 + TOPK / 4; k++) {
        float w = s_w[k];
        if (w > 0.f) {
            int n   = s_i[k];
            int b   = n >> 18;
            int rem = n & (HH * WW - 1);
            int Y = rem >> 9;
            int X = rem & 511;
            int y0, y1, x0, x1; float fy, fx;
            src_coord(Y, y0, y1, fy);
            src_coord(X, x0, x1, fx);
            const float* base = g_fT + ((size_t)b * SPIX) * DIM;
            const float* p00 = base + ((size_t)(y0 * WF + x0)) * DIM;
            const float* p01 = base + ((size_t)(y0 * WF + x1)) * DIM;
            const float* p10 = base + ((size_t)(y1 * WF + x0)) * DIM;
            const float* p11 = base + ((size_t)(y1 * WF + x1)) * DIM;
            float w00 = (1.f - fy) * (1.f - fx);
            float w01 = (1.f - fy) * fx;
            float w10 = fy * (1.f - fx);
            float w11 = fy * fx;
            float v = w00 * __ldg(p00 + d) + w01 * __ldg(p01 + d)
                    + w10 * __ldg(p10 + d) + w11 * __ldg(p11 + d);
            acc += w * v;
        }
    }
    red[t] = acc;
    __syncthreads();

    // ---- normalize, EMA, normalize, write (red reused for 256-wide reductions) ----
    float proto = 0.f;
    if (t < DIM) {
        float tot = red[d] + red[d + 256] + red[d + 512] + red[d + 768];
        proto = tot / fmaxf(wsum, EPSV);
        red[d] = proto * proto;        // safe: each t<256 reads its own lanes first
    }
    __syncthreads();
    for (int s = 128; s > 0; s >>= 1) {
        if (t < s) red[t] += red[t + s];
        __syncthreads();
    }
    float nrm = sqrtf(red[0]);
    __syncthreads();

    bool has = (L > 0) && (wsum > 0.f);
    float uc = update_count[c];
    float gamma = (uc == 0.f) ? 0.f : fminf(1.f - 1.f / (uc + 1.f), GAMMA_MAX);
    float nv = 0.f;
    if (t < DIM) {
        proto = proto / fmaxf(nrm, EPSV);
        float oldp = prototypes[c * DIM + d];
        nv = has ? (gamma * oldp + (1.f - gamma) * proto) : oldp;
        red[d] = nv * nv;
    }
    __syncthreads();
    for (int s = 128; s > 0; s >>= 1) {
        if (t < s) red[t] += red[t + s];
        __syncthreads();
    }
    float nrm2 = sqrtf(red[0]);
    if (t < DIM)
        out[c * DIM + d] = nv / fmaxf(nrm2, EPSV);
    if (t == 0) {
        if (out_size >= NC * DIM + NC)
            out[NC * DIM + c] = uc + (has ? 1.f : 0.f);
        g_cnt[c] = 0;   // cleanup for next graph replay
    }
}

// ---------------- launch ----------------
extern "C" void kernel_launch(void* const* d_in, const int* in_sizes, int n_in,
                              void* d_out, int out_size) {
    const float* features     = (const float*)d_in[0];
    const float* weight       = (const float*)d_in[1];
    const float* prototypes   = (const float*)d_in[2];
    const float* update_count = (const float*)d_in[3];
    const int*   labels       = (const int*)d_in[4];
    float* out = (float*)d_out;

    k_main<<<TRANS_BLOCKS + WT_BLOCKS, 256>>>(features, weight, labels);
    k_tail<<<NC, 1024>>>(prototypes, update_count, out, out_size);
}

// round 6
// speedup vs baseline: 4.6346x; 1.3703x over previous
#include <cuda_runtime.h>
#include <cuda_bf16.h>
#include <math.h>

#define BATCH 2
#define DIM   256
#define NC    19
#define TOPK  256
#define HF    128
#define WF    128
#define HH    512
#define WW    512
#define SPIX  (HF*WF)            // 16384
#define NPIX  (BATCH*HH*WW)      // 524288
#define EPSV  1e-12f
#define GAMMA_MAX 0.999f
#define NB    8192               // histogram bins over w in [0,1)
#define CCAP  2048               // shared candidate capacity (threshold bin)

#define TRANS_BLOCKS 8192        // 512 * 8 * 2
#define WT_BLOCKS    2048        // NPIX / 256

// ---------------- scratch (static device memory; zero-init at load) ----------------
__device__ __align__(16) float g_fT[(size_t)BATCH*SPIX*DIM]; // features [B, HF*WF, DIM]
__device__ float g_cw[(size_t)NC*NPIX];          // per-class weight lists
__device__ int   g_cidx[(size_t)NC*NPIX];        // per-class pixel-index lists
__device__ int   g_cnt[NC];                      // per-class list counts

// ---------------- helpers ----------------
__device__ __forceinline__ void src_coord(int o, int &i0, int &i1, float &f) {
    float s = (o + 0.5f) * 0.25f - 0.5f;
    float fl = floorf(s);
    f = s - fl;
    int i = (int)fl;
    i0 = min(max(i, 0), HF - 1);
    i1 = min(max(i + 1, 0), HF - 1);
}

__device__ __forceinline__ int w_bin(float w) {
    int b = (int)(w * (float)NB);
    return min(NB - 1, max(0, b));
}

// ================= K1: fused transpose + weights/list append =================
__global__ void k_main(const float* __restrict__ f,
                       const float* __restrict__ weight,
                       const int* __restrict__ labels) {
    if (blockIdx.x < TRANS_BLOCKS) {
        // ---- NCHW -> NHWC transpose ----
        __shared__ float tile[32][33];
        int i = blockIdx.x;
        int s0 = (i & 511) * 32;
        int d0 = ((i >> 9) & 7) * 32;
        int b  = i >> 12;
        int tx = threadIdx.x & 31;
        int ty = threadIdx.x >> 5;           // 0..7
        #pragma unroll
        for (int r = ty; r < 32; r += 8)
            tile[r][tx] = f[((size_t)(b * DIM + d0 + r)) * SPIX + s0 + tx];
        __syncthreads();
        #pragma unroll
        for (int r = ty; r < 32; r += 8)
            g_fT[((size_t)(b * SPIX + s0 + r)) * DIM + d0 + tx] = tile[tx][r];
    } else {
        // ---- per-pixel weight + per-class list append ----
        __shared__ int s_cnt[NC];
        __shared__ int s_base[NC];
        int n = (blockIdx.x - TRANS_BLOCKS) * 256 + threadIdx.x;
        if (threadIdx.x < NC) s_cnt[threadIdx.x] = 0;
        __syncthreads();

        int lab = labels[n];
        bool valid = ((unsigned)lab < NC);
        float w = 0.f;
        int r = 0;
        if (valid) {
            int b   = n >> 18;
            int rem = n & (HH * WW - 1);
            int Y = rem >> 9;
            int X = rem & 511;
            int y0, y1, x0, x1; float fy, fx;
            src_coord(Y, y0, y1, fy);
            src_coord(X, x0, x1, fx);
            const float* wp = weight + ((size_t)(b * NC + lab)) * SPIX;
            float v00 = __ldg(wp + y0 * WF + x0);
            float v01 = __ldg(wp + y0 * WF + x1);
            float v10 = __ldg(wp + y1 * WF + x0);
            float v11 = __ldg(wp + y1 * WF + x1);
            w = (1.f - fy) * ((1.f - fx) * v00 + fx * v01)
              +        fy  * ((1.f - fx) * v10 + fx * v11);
            r = atomicAdd(&s_cnt[lab], 1);
        }
        __syncthreads();
        if (threadIdx.x < NC && s_cnt[threadIdx.x] > 0)
            s_base[threadIdx.x] = atomicAdd(&g_cnt[threadIdx.x], s_cnt[threadIdx.x]);
        __syncthreads();
        if (valid) {
            size_t o = (size_t)lab * NPIX + (size_t)(s_base[lab] + r);
            g_cw[o]   = w;
            g_cidx[o] = n;
        }
    }
}

// ================= K2: hist + threshold + partition + fill + accumulate + finalize =================
__global__ void __launch_bounds__(1024) k_tail(
        const float* __restrict__ prototypes,
        const float* __restrict__ update_count,
        float* __restrict__ out, int out_size) {
    int c = blockIdx.x;
    int t = threadIdx.x;

    __shared__ int   hist[NB];        // 32 KB; reused as candidate store later
    __shared__ float s_w[TOPK];
    __shared__ int   s_i[TOPK];
    __shared__ int   P[1024];         // scan workspace
    __shared__ float4 redv[1024];     // float4 reduction workspace (16 KB)
    __shared__ int s_nsel, s_ncand, s_tb, s_above;

    float* red = (float*)redv;        // scalar view for small reductions

    int L = g_cnt[c];
    const float* cw = g_cw   + (size_t)c * NPIX;
    const int*   ci = g_cidx + (size_t)c * NPIX;

    #pragma unroll
    for (int i = t; i < NB; i += 1024) hist[i] = 0;
    if (t == 0) { s_nsel = 0; s_ncand = 0; s_tb = -1; s_above = 0; }
    __syncthreads();

    // ---- pass 1: local histogram of this class's weights ----
    for (int i = t; i < L; i += 1024)
        atomicAdd(&hist[w_bin(cw[i])], 1);
    __syncthreads();

    // ---- parallel threshold-bin discovery (only needed if L > TOPK) ----
    if (L > TOPK) {
        int base = NB - (t + 1) * 8;          // 8 bins per thread, top-down chunks
        int s = 0;
        #pragma unroll
        for (int b = 0; b < 8; b++) s += hist[base + b];
        P[t] = s;
        __syncthreads();
        // Hillis-Steele inclusive scan over 1024 chunk sums (descending-bin order)
        #pragma unroll
        for (int off = 1; off < 1024; off <<= 1) {
            int v = (t >= off) ? P[t - off] : 0;
            __syncthreads();
            P[t] += v;
            __syncthreads();
        }
        if (P[t] >= TOPK && (t == 0 || P[t - 1] < TOPK)) {
            int acc = (t == 0) ? 0 : P[t - 1];
            for (int b = NB - t * 8 - 1; b >= base; b--) {
                int h = hist[b];
                if (acc + h >= TOPK) { s_tb = b; s_above = acc; break; }
                acc += h;
            }
        }
        __syncthreads();
    }
    int tb = s_tb;                     // -1 => take everything

    // ---- pass 2: partition (hist storage reused for candidates) ----
    float* s_cw = (float*)hist;        // [0 .. CCAP)
    int*   s_ci = hist + CCAP;         // [CCAP .. 2*CCAP)
    for (int i = t; i < L; i += 1024) {
        float w = cw[i];
        int bin = w_bin(w);
        if (bin > tb) {
            int p = atomicAdd(&s_nsel, 1);     // guaranteed < TOPK
            s_w[p] = w; s_i[p] = ci[i];
        } else if (bin == tb) {
            int q = atomicAdd(&s_ncand, 1);
            if (q < CCAP) { s_cw[q] = w; s_ci[q] = ci[i]; }
        }
    }
    __syncthreads();

    // ---- parallel rank select to fill remaining slots from threshold bin ----
    int above = s_nsel;
    int r = TOPK - above;
    int L2 = min(s_ncand, CCAP);
    int nsel = above + ((r > 0) ? min(r, L2) : 0);
    if (r > 0) {
        for (int i = t; i < L2; i += 1024) {
            float wi = s_cw[i];
            int rank = 0;
            for (int j = 0; j < L2; j++) {
                float wj = s_cw[j];
                rank += (wj > wi) || (wj == wi && j < i);
            }
            if (rank < r) { s_w[above + rank] = wi; s_i[above + rank] = s_ci[i]; }
        }
    }
    __syncthreads();

    // ---- pad unused slots ----
    for (int i = t; i < TOPK; i += 1024)
        if (i >= nsel) { s_w[i] = 0.f; s_i[i] = 0; }
    __syncthreads();

    // ---- weight sum ----
    red[t] = (t < TOPK) ? s_w[t] : 0.f;
    __syncthreads();
    for (int s = 512; s > 0; s >>= 1) {
        if (t < s) red[t] += red[t + s];
        __syncthreads();
    }
    float wsum = red[0];
    __syncthreads();

    // ---- weighted feature accumulation (float4 gather) ----
    // thread = (part 0..15, d4 0..63); d4 covers dims [4*d4, 4*d4+4)
    int d4   = t & 63;
    int part = t >> 6;
    float4 acc = make_float4(0.f, 0.f, 0.f, 0.f);
    int k0 = part * (TOPK / 16);
    #pragma unroll 4
    for (int k = k0; k < k0 + TOPK / 16; k++) {
        float w = s_w[k];
        if (w > 0.f) {
            int n   = s_i[k];
            int b   = n >> 18;
            int rem = n & (HH * WW - 1);
            int Y = rem >> 9;
            int X = rem & 511;
            int y0, y1, x0, x1; float fy, fx;
            src_coord(Y, y0, y1, fy);
            src_coord(X, x0, x1, fx);
            const float4* base = (const float4*)(g_fT + ((size_t)b * SPIX) * DIM);
            const float4* p00 = base + (size_t)(y0 * WF + x0) * (DIM / 4) + d4;
            const float4* p01 = base + (size_t)(y0 * WF + x1) * (DIM / 4) + d4;
            const float4* p10 = base + (size_t)(y1 * WF + x0) * (DIM / 4) + d4;
            const float4* p11 = base + (size_t)(y1 * WF + x1) * (DIM / 4) + d4;
            float4 v00 = __ldg(p00);
            float4 v01 = __ldg(p01);
            float4 v10 = __ldg(p10);
            float4 v11 = __ldg(p11);
            float w00 = (1.f - fy) * (1.f - fx);
            float w01 = (1.f - fy) * fx;
            float w10 = fy * (1.f - fx);
            float w11 = fy * fx;
            acc.x += w * (w00 * v00.x + w01 * v01.x + w10 * v10.x + w11 * v11.x);
            acc.y += w * (w00 * v00.y + w01 * v01.y + w10 * v10.y + w11 * v11.y);
            acc.z += w * (w00 * v00.z + w01 * v01.z + w10 * v10.z + w11 * v11.z);
            acc.w += w * (w00 * v00.w + w01 * v01.w + w10 * v10.w + w11 * v11.w);
        }
    }
    redv[part * 64 + d4] = acc;
    __syncthreads();
    // tree-reduce over the 16 parts (float4 lanes)
    #pragma unroll
    for (int s = 8; s >= 1; s >>= 1) {
        if (part < s) {
            float4 a = redv[part * 64 + d4];
            float4 bq = redv[(part + s) * 64 + d4];
            a.x += bq.x; a.y += bq.y; a.z += bq.z; a.w += bq.w;
            redv[part * 64 + d4] = a;
        }
        __syncthreads();
    }
    // redv[0..63] flattened = dims 0..255

    // ---- normalize, EMA, normalize, write ----
    int d = t;                        // t < 256 handles dim d
    float proto = 0.f;
    if (t < DIM) {
        float tot = red[d];           // scalar view of redv[0..63]
        proto = tot / fmaxf(wsum, EPSV);
    }
    __syncthreads();
    if (t < DIM) red[d] = proto * proto;
    __syncthreads();
    for (int s = 128; s > 0; s >>= 1) {
        if (t < s) red[t] += red[t + s];
        __syncthreads();
    }
    float nrm = sqrtf(red[0]);
    __syncthreads();

    bool has = (L > 0) && (wsum > 0.f);
    float uc = update_count[c];
    float gamma = (uc == 0.f) ? 0.f : fminf(1.f - 1.f / (uc + 1.f), GAMMA_MAX);
    float nv = 0.f;
    if (t < DIM) {
        proto = proto / fmaxf(nrm, EPSV);
        float oldp = prototypes[c * DIM + d];
        nv = has ? (gamma * oldp + (1.f - gamma) * proto) : oldp;
        red[d] = nv * nv;
    }
    __syncthreads();
    for (int s = 128; s > 0; s >>= 1) {
        if (t < s) red[t] += red[t + s];
        __syncthreads();
    }
    float nrm2 = sqrtf(red[0]);
    if (t < DIM)
        out[c * DIM + d] = nv / fmaxf(nrm2, EPSV);
    if (t == 0) {
        if (out_size >= NC * DIM + NC)
            out[NC * DIM + c] = uc + (has ? 1.f : 0.f);
        g_cnt[c] = 0;   // cleanup for next graph replay
    }
}

// ---------------- launch ----------------
extern "C" void kernel_launch(void* const* d_in, const int* in_sizes, int n_in,
                              void* d_out, int out_size) {
    const float* features     = (const float*)d_in[0];
    const float* weight       = (const float*)d_in[1];
    const float* prototypes   = (const float*)d_in[2];
    const float* update_count = (const float*)d_in[3];
    const int*   labels       = (const int*)d_in[4];
    float* out = (float*)d_out;

    k_main<<<TRANS_BLOCKS + WT_BLOCKS, 256>>>(features, weight, labels);
    k_tail<<<NC, 1024>>>(prototypes, update_count, out, out_size);
}

// round 7
// speedup vs baseline: 5.0887x; 1.0980x over previous
#include <cuda_runtime.h>
#include <cuda_bf16.h>
#include <math.h>

#define BATCH 2
#define DIM   256
#define NC    19
#define TOPK  256
#define HF    128
#define WF    128
#define HH    512
#define WW    512
#define SPIX  (HF*WF)            // 16384
#define NPIX  (BATCH*HH*WW)      // 524288
#define EPSV  1e-12f
#define GAMMA_MAX 0.999f
#define NB    8192               // histogram bins over w in [0,1)
#define CCAP  2048               // shared candidate capacity (threshold bin)
#define GPARTS 8                 // gather blocks per class

#define TRANS_BLOCKS 8192        // 512 * 8 * 2
#define WT_BLOCKS    2048        // NPIX / 256

// ---------------- scratch (static device memory; zero-init at load) ----------------
__device__ __align__(16) float g_fT[(size_t)BATCH*SPIX*DIM]; // features [B, HF*WF, DIM]
__device__ __align__(16) float g_cw[(size_t)NC*NPIX];        // per-class weight lists
__device__ __align__(16) int   g_cidx[(size_t)NC*NPIX];      // per-class pixel-index lists
__device__ int   g_cnt[NC];                      // per-class list counts
__device__ float g_selw[NC*TOPK];                // selected weights
__device__ int   g_seli[NC*TOPK];                // selected pixel indices
__device__ float g_wsum[NC];                     // selected weight sums
__device__ int   g_has[NC];                      // class-present flags
__device__ __align__(16) float g_part[NC*GPARTS*DIM]; // gather partials
__device__ unsigned g_done[NC];                  // gather completion tickets

// ---------------- helpers ----------------
__device__ __forceinline__ void src_coord(int o, int &i0, int &i1, float &f) {
    float s = (o + 0.5f) * 0.25f - 0.5f;
    float fl = floorf(s);
    f = s - fl;
    int i = (int)fl;
    i0 = min(max(i, 0), HF - 1);
    i1 = min(max(i + 1, 0), HF - 1);
}

__device__ __forceinline__ int w_bin(float w) {
    int b = (int)(w * (float)NB);
    return min(NB - 1, max(0, b));
}

// ================= K1: fused transpose + weights/list append =================
__global__ void k_main(const float* __restrict__ f,
                       const float* __restrict__ weight,
                       const int* __restrict__ labels) {
    if (blockIdx.x < TRANS_BLOCKS) {
        __shared__ float tile[32][33];
        int i = blockIdx.x;
        int s0 = (i & 511) * 32;
        int d0 = ((i >> 9) & 7) * 32;
        int b  = i >> 12;
        int tx = threadIdx.x & 31;
        int ty = threadIdx.x >> 5;
        #pragma unroll
        for (int r = ty; r < 32; r += 8)
            tile[r][tx] = f[((size_t)(b * DIM + d0 + r)) * SPIX + s0 + tx];
        __syncthreads();
        #pragma unroll
        for (int r = ty; r < 32; r += 8)
            g_fT[((size_t)(b * SPIX + s0 + r)) * DIM + d0 + tx] = tile[tx][r];
    } else {
        __shared__ int s_cnt[NC];
        __shared__ int s_base[NC];
        int n = (blockIdx.x - TRANS_BLOCKS) * 256 + threadIdx.x;
        if (threadIdx.x < NC) s_cnt[threadIdx.x] = 0;
        __syncthreads();

        int lab = labels[n];
        bool valid = ((unsigned)lab < NC);
        float w = 0.f;
        int r = 0;
        if (valid) {
            int b   = n >> 18;
            int rem = n & (HH * WW - 1);
            int Y = rem >> 9;
            int X = rem & 511;
            int y0, y1, x0, x1; float fy, fx;
            src_coord(Y, y0, y1, fy);
            src_coord(X, x0, x1, fx);
            const float* wp = weight + ((size_t)(b * NC + lab)) * SPIX;
            float v00 = __ldg(wp + y0 * WF + x0);
            float v01 = __ldg(wp + y0 * WF + x1);
            float v10 = __ldg(wp + y1 * WF + x0);
            float v11 = __ldg(wp + y1 * WF + x1);
            w = (1.f - fy) * ((1.f - fx) * v00 + fx * v01)
              +        fy  * ((1.f - fx) * v10 + fx * v11);
            r = atomicAdd(&s_cnt[lab], 1);
        }
        __syncthreads();
        if (threadIdx.x < NC && s_cnt[threadIdx.x] > 0)
            s_base[threadIdx.x] = atomicAdd(&g_cnt[threadIdx.x], s_cnt[threadIdx.x]);
        __syncthreads();
        if (valid) {
            size_t o = (size_t)lab * NPIX + (size_t)(s_base[lab] + r);
            g_cw[o]   = w;
            g_cidx[o] = n;
        }
    }
}

// ================= K2: per-class exact top-256 selection =================
__global__ void __launch_bounds__(1024) k_select() {
    int c = blockIdx.x;
    int t = threadIdx.x;

    __shared__ int   hist[NB];        // 32 KB; reused as candidate store
    __shared__ float s_w[TOPK];
    __shared__ int   s_i[TOPK];
    __shared__ int   P[1024];
    __shared__ float red[256];
    __shared__ int s_nsel, s_ncand, s_tb;

    int L = g_cnt[c];
    const float* cw = g_cw   + (size_t)c * NPIX;
    const int*   ci = g_cidx + (size_t)c * NPIX;

    if (t == 0) { s_nsel = 0; s_ncand = 0; s_tb = -1; }

    if (L <= TOPK) {
        __syncthreads();
        for (int i = t; i < TOPK; i += 1024) {
            if (i < L) { s_w[i] = cw[i]; s_i[i] = ci[i]; }
            else       { s_w[i] = 0.f;   s_i[i] = 0; }
        }
        __syncthreads();
    } else {
        #pragma unroll
        for (int i = t; i < NB; i += 1024) hist[i] = 0;
        __syncthreads();

        // ---- pass 1: histogram (float4 vectorized) ----
        int L4 = L & ~3;
        for (int i = t * 4; i < L4; i += 4096) {
            float4 v = *(const float4*)(cw + i);
            atomicAdd(&hist[w_bin(v.x)], 1);
            atomicAdd(&hist[w_bin(v.y)], 1);
            atomicAdd(&hist[w_bin(v.z)], 1);
            atomicAdd(&hist[w_bin(v.w)], 1);
        }
        for (int i = L4 + t; i < L; i += 1024)
            atomicAdd(&hist[w_bin(cw[i])], 1);
        __syncthreads();

        // ---- threshold-bin discovery (parallel scan) ----
        {
            int base = NB - (t + 1) * 8;
            int s = 0;
            #pragma unroll
            for (int b = 0; b < 8; b++) s += hist[base + b];
            P[t] = s;
            __syncthreads();
            #pragma unroll
            for (int off = 1; off < 1024; off <<= 1) {
                int v = (t >= off) ? P[t - off] : 0;
                __syncthreads();
                P[t] += v;
                __syncthreads();
            }
            if (P[t] >= TOPK && (t == 0 || P[t - 1] < TOPK)) {
                int acc = (t == 0) ? 0 : P[t - 1];
                for (int b = NB - t * 8 - 1; b >= base; b--) {
                    int h = hist[b];
                    if (acc + h >= TOPK) { s_tb = b; break; }
                    acc += h;
                }
            }
            __syncthreads();
        }
        int tb = s_tb;

        // ---- pass 2: partition (vectorized; hist reused as candidate store) ----
        float* s_cw = (float*)hist;
        int*   s_ci = hist + CCAP;
        for (int i = t * 4; i < L4; i += 4096) {
            float4 v = *(const float4*)(cw + i);
            int4   x = *(const int4*)(ci + i);
            float wv[4] = {v.x, v.y, v.z, v.w};
            int   iv[4] = {x.x, x.y, x.z, x.w};
            #pragma unroll
            for (int j = 0; j < 4; j++) {
                int bin = w_bin(wv[j]);
                if (bin > tb) {
                    int p = atomicAdd(&s_nsel, 1);
                    s_w[p] = wv[j]; s_i[p] = iv[j];
                } else if (bin == tb) {
                    int q = atomicAdd(&s_ncand, 1);
                    if (q < CCAP) { s_cw[q] = wv[j]; s_ci[q] = iv[j]; }
                }
            }
        }
        for (int i = L4 + t; i < L; i += 1024) {
            float w = cw[i];
            int bin = w_bin(w);
            if (bin > tb) {
                int p = atomicAdd(&s_nsel, 1);
                s_w[p] = w; s_i[p] = ci[i];
            } else if (bin == tb) {
                int q = atomicAdd(&s_ncand, 1);
                if (q < CCAP) { s_cw[q] = w; s_ci[q] = ci[i]; }
            }
        }
        __syncthreads();

        // ---- parallel rank select from threshold bin ----
        int above = s_nsel;
        int r = TOPK - above;
        int L2 = min(s_ncand, CCAP);
        if (r > 0) {
            for (int i = t; i < L2; i += 1024) {
                float wi = s_cw[i];
                int rank = 0;
                for (int j = 0; j < L2; j++) {
                    float wj = s_cw[j];
                    rank += (wj > wi) || (wj == wi && j < i);
                }
                if (rank < r) { s_w[above + rank] = wi; s_i[above + rank] = s_ci[i]; }
            }
        }
        int nsel = above + ((r > 0) ? min(r, L2) : 0);
        __syncthreads();
        for (int i = t; i < TOPK; i += 1024)
            if (i >= nsel) { s_w[i] = 0.f; s_i[i] = 0; }
        __syncthreads();
    }

    // ---- weight sum + write selection to global ----
    if (t < TOPK) {
        red[t] = s_w[t];
        g_selw[c * TOPK + t] = s_w[t];
        g_seli[c * TOPK + t] = s_i[t];
    }
    __syncthreads();
    if (t < 128) {
        #pragma unroll
        for (int s = 128; s > 0; s >>= 1) {
            if (t < s) red[t] += red[t + s];
            __syncwarp(0xFFFFFFFFu);
            if (s > 32) __syncthreads();
        }
    }
    __syncthreads();
    if (t == 0) {
        float wsum = red[0];
        g_wsum[c] = wsum;
        g_has[c]  = (L > 0) && (wsum > 0.f);
        g_cnt[c]  = 0;             // cleanup for next graph replay
    }
}

// ================= K3: gather partials + last-block finalize =================
__global__ void __launch_bounds__(256) k_gather(
        const float* __restrict__ prototypes,
        const float* __restrict__ update_count,
        float* __restrict__ out, int out_size) {
    int c = blockIdx.x >> 3;           // class
    int p = blockIdx.x & (GPARTS - 1); // part: 32 pixels
    int t = threadIdx.x;
    int d4  = t & 63;                  // float4 dim group
    int sub = t >> 6;                  // 0..3, 8 pixels each

    __shared__ float4 sv[256];
    __shared__ float red[256];
    __shared__ int s_last;

    float4 acc = make_float4(0.f, 0.f, 0.f, 0.f);
    int k0 = p * 32 + sub * 8;
    #pragma unroll
    for (int k = k0; k < k0 + 8; k++) {
        float w = g_selw[c * TOPK + k];
        if (w > 0.f) {
            int n   = g_seli[c * TOPK + k];
            int b   = n >> 18;
            int rem = n & (HH * WW - 1);
            int Y = rem >> 9;
            int X = rem & 511;
            int y0, y1, x0, x1; float fy, fx;
            src_coord(Y, y0, y1, fy);
            src_coord(X, x0, x1, fx);
            const float4* base = (const float4*)(g_fT + ((size_t)b * SPIX) * DIM);
            float4 v00 = __ldg(base + (size_t)(y0 * WF + x0) * (DIM / 4) + d4);
            float4 v01 = __ldg(base + (size_t)(y0 * WF + x1) * (DIM / 4) + d4);
            float4 v10 = __ldg(base + (size_t)(y1 * WF + x0) * (DIM / 4) + d4);
            float4 v11 = __ldg(base + (size_t)(y1 * WF + x1) * (DIM / 4) + d4);
            float w00 = (1.f - fy) * (1.f - fx);
            float w01 = (1.f - fy) * fx;
            float w10 = fy * (1.f - fx);
            float w11 = fy * fx;
            acc.x += w * (w00 * v00.x + w01 * v01.x + w10 * v10.x + w11 * v11.x);
            acc.y += w * (w00 * v00.y + w01 * v01.y + w10 * v10.y + w11 * v11.y);
            acc.z += w * (w00 * v00.z + w01 * v01.z + w10 * v10.z + w11 * v11.z);
            acc.w += w * (w00 * v00.w + w01 * v01.w + w10 * v10.w + w11 * v11.w);
        }
    }
    sv[t] = acc;
    __syncthreads();
    if (sub < 2) {
        float4 a = sv[t], bq = sv[t + 128];
        a.x += bq.x; a.y += bq.y; a.z += bq.z; a.w += bq.w;
        sv[t] = a;
    }
    __syncthreads();
    if (sub == 0) {
        float4 a = sv[t], bq = sv[t + 64];
        a.x += bq.x; a.y += bq.y; a.z += bq.z; a.w += bq.w;
        ((float4*)g_part)[(c * GPARTS + p) * (DIM / 4) + d4] = a;
    }
    __threadfence();
    __syncthreads();
    if (t == 0)
        s_last = (atomicAdd(&g_done[c], 1u) == GPARTS - 1u);
    __syncthreads();
    if (!s_last) return;

    // ---- finalize (only the last block of this class) ----
    __threadfence();
    int d = t;                        // 256 threads = 256 dims
    float tot = 0.f;
    #pragma unroll
    for (int q = 0; q < GPARTS; q++)
        tot += g_part[(c * GPARTS + q) * DIM + d];

    float wsum = g_wsum[c];
    float proto = tot / fmaxf(wsum, EPSV);

    red[d] = proto * proto;
    __syncthreads();
    for (int s = 128; s > 0; s >>= 1) {
        if (t < s) red[t] += red[t + s];
        __syncthreads();
    }
    float nrm = sqrtf(red[0]);
    __syncthreads();
    proto = proto / fmaxf(nrm, EPSV);

    bool has = g_has[c] != 0;
    float uc = update_count[c];
    float gamma = (uc == 0.f) ? 0.f : fminf(1.f - 1.f / (uc + 1.f), GAMMA_MAX);
    float oldp = prototypes[c * DIM + d];
    float nv = has ? (gamma * oldp + (1.f - gamma) * proto) : oldp;

    red[d] = nv * nv;
    __syncthreads();
    for (int s = 128; s > 0; s >>= 1) {
        if (t < s) red[t] += red[t + s];
        __syncthreads();
    }
    float nrm2 = sqrtf(red[0]);
    out[c * DIM + d] = nv / fmaxf(nrm2, EPSV);
    if (t == 0) {
        if (out_size >= NC * DIM + NC)
            out[NC * DIM + c] = uc + (has ? 1.f : 0.f);
        g_done[c] = 0u;   // cleanup for next graph replay
    }
}

// ---------------- launch ----------------
extern "C" void kernel_launch(void* const* d_in, const int* in_sizes, int n_in,
                              void* d_out, int out_size) {
    const float* features     = (const float*)d_in[0];
    const float* weight       = (const float*)d_in[1];
    const float* prototypes   = (const float*)d_in[2];
    const float* update_count = (const float*)d_in[3];
    const int*   labels       = (const int*)d_in[4];
    float* out = (float*)d_out;

    k_main<<<TRANS_BLOCKS + WT_BLOCKS, 256>>>(features, weight, labels);
    k_select<<<NC, 1024>>>();
    k_gather<<<NC * GPARTS, 256>>>(prototypes, update_count, out, out_size);
}